// round 1
// baseline (speedup 1.0000x reference)
#include <cuda_runtime.h>

// Problem dims (fixed by the dataset)
#define Bz 4096
#define Iz 256
#define Oz 256
#define Gz 16
#define Kz 8192   // Iz * 2 * Gz

// Scratch (device globals: allocation-free per harness rules)
__device__ float g_F[(size_t)Bz * Kz];   // features, row-major [B][K], 128 MB
__device__ float g_W[(size_t)Kz * Oz];   // transposed weights [K][O], 8 MB

// ---------------------------------------------------------------------------
// Kernel 1: feature generation.
// k = i*32 + s*16 + g ;  s=0 -> exp(-lambda*x) (pairs coeff[0]),
//                        s=1 -> exp(+lambda*x) (pairs coeff[1]).
// lambda_g = 0.1 + 0.06*g  => geometric recurrence: only 4 __expf per (b,i).
// ---------------------------------------------------------------------------
__global__ __launch_bounds__(256) void feat_kernel(const float* __restrict__ x) {
    int idx = blockIdx.x * 256 + threadIdx.x;       // idx = b*Iz + i
    if (idx >= Bz * Iz) return;
    float xv = x[idx];

    float tneg = __expf(-0.06f * xv);
    float tpos = __expf( 0.06f * xv);
    float fn   = __expf(-0.10f * xv);   // lambda_0 = 0.1
    float fp   = __expf( 0.10f * xv);

    float buf[32];
#pragma unroll
    for (int g = 0; g < 16; g++) {
        buf[g]      = fn;
        buf[16 + g] = fp;
        fn *= tneg;
        fp *= tpos;
    }

    // F row b, cols [i*32, i*32+32)  =>  linear offset idx*32 (since Kz = Iz*32)
    float4* dst = reinterpret_cast<float4*>(g_F + (size_t)idx * 32);
    const float4* src = reinterpret_cast<const float4*>(buf);
#pragma unroll
    for (int q = 0; q < 8; q++) dst[q] = src[q];
}

// ---------------------------------------------------------------------------
// Kernel 2: weight transpose/gather.
// coeff layout: [2][O][I][G] (g contiguous). Build W[k][o], o contiguous.
// One block per (i, s) pair; thread = o. Reads 64B contiguous per thread
// (full sectors), writes coalesced across o.
// ---------------------------------------------------------------------------
__global__ __launch_bounds__(256) void wtrans_kernel(const float* __restrict__ C) {
    int i = blockIdx.x >> 1;
    int s = blockIdx.x & 1;
    int o = threadIdx.x;

    const float4* src = reinterpret_cast<const float4*>(
        C + (((size_t)s * Oz + o) * Iz + i) * Gz);
    float vals[16];
#pragma unroll
    for (int q = 0; q < 4; q++) {
        float4 v = src[q];
        vals[q * 4 + 0] = v.x; vals[q * 4 + 1] = v.y;
        vals[q * 4 + 2] = v.z; vals[q * 4 + 3] = v.w;
    }
    int kbase = i * 32 + s * 16;
#pragma unroll
    for (int g = 0; g < 16; g++)
        g_W[(size_t)(kbase + g) * Oz + o] = vals[g];
}

// ---------------------------------------------------------------------------
// Kernel 3: fp32 SGEMM  out[B][O] = F[B][K] * W[K][O] + bias[O]
// 128x64 CTA tile, BK=16, 256 threads, 8x4 per thread, register prefetch.
// Grid: (Oz/64, Bz/128) = (4, 32) = 128 CTAs.
// ---------------------------------------------------------------------------
#define BM 128
#define BN 64
#define BK 16
#define TM 8
#define TN 4

__global__ __launch_bounds__(256) void gemm_kernel(const float* __restrict__ bias,
                                                   float* __restrict__ out) {
    __shared__ float As[BK][BM];   // 8 KB  (k-major for conflict-free reads)
    __shared__ float Bs[BK][BN];   // 4 KB

    int tid = threadIdx.x;
    int tx  = tid & 15;            // n group (0..15) -> 4 cols each
    int ty  = tid >> 4;            // m group (0..15) -> 8 rows each
    int m0  = blockIdx.y * BM;
    int n0  = blockIdx.x * BN;

    // A tile load mapping: 128 rows x 16 k; each thread: 1 row, 8 consecutive k
    int a_row = tid & 127;
    int a_k   = (tid >> 7) << 3;   // 0 or 8
    const float* Aptr = g_F + (size_t)(m0 + a_row) * Kz + a_k;

    // B tile load mapping: 16 k-rows x 64 o; each thread: one float4
    int b_k = tid >> 4;            // 0..15
    int b_o = (tid & 15) << 2;     // 0..60
    const float* Bbase = g_W + n0 + b_o;

    float acc[TM][TN];
#pragma unroll
    for (int m = 0; m < TM; m++)
#pragma unroll
        for (int n = 0; n < TN; n++) acc[m][n] = 0.0f;

    // prologue: fetch tile 0 into registers
    float4 ar0 = *reinterpret_cast<const float4*>(Aptr);
    float4 ar1 = *reinterpret_cast<const float4*>(Aptr + 4);
    float4 br  = *reinterpret_cast<const float4*>(Bbase + (size_t)b_k * Oz);

    const int NT = Kz / BK;        // 512 k-tiles
    for (int kt = 0; kt < NT; kt++) {
        // commit prefetched tile to smem
        As[a_k + 0][a_row] = ar0.x;
        As[a_k + 1][a_row] = ar0.y;
        As[a_k + 2][a_row] = ar0.z;
        As[a_k + 3][a_row] = ar0.w;
        As[a_k + 4][a_row] = ar1.x;
        As[a_k + 5][a_row] = ar1.y;
        As[a_k + 6][a_row] = ar1.z;
        As[a_k + 7][a_row] = ar1.w;
        *reinterpret_cast<float4*>(&Bs[b_k][b_o]) = br;
        __syncthreads();

        // prefetch next tile (hidden under the FMA loop below)
        if (kt + 1 < NT) {
            const float* An = Aptr + (size_t)(kt + 1) * BK;
            ar0 = *reinterpret_cast<const float4*>(An);
            ar1 = *reinterpret_cast<const float4*>(An + 4);
            br  = *reinterpret_cast<const float4*>(
                      Bbase + (size_t)((kt + 1) * BK + b_k) * Oz);
        }

        // compute 16 k-steps
#pragma unroll
        for (int kk = 0; kk < BK; kk++) {
            float4 a0 = *reinterpret_cast<const float4*>(&As[kk][ty * TM]);
            float4 a1 = *reinterpret_cast<const float4*>(&As[kk][ty * TM + 4]);
            float4 bq = *reinterpret_cast<const float4*>(&Bs[kk][tx * TN]);
            float am[TM] = {a0.x, a0.y, a0.z, a0.w, a1.x, a1.y, a1.z, a1.w};
            float bn[TN] = {bq.x, bq.y, bq.z, bq.w};
#pragma unroll
            for (int m = 0; m < TM; m++)
#pragma unroll
                for (int n = 0; n < TN; n++)
                    acc[m][n] += am[m] * bn[n];
        }
        __syncthreads();
    }

    // epilogue: add bias, write out
    float bv[TN];
#pragma unroll
    for (int n = 0; n < TN; n++) bv[n] = bias[n0 + tx * TN + n];

#pragma unroll
    for (int m = 0; m < TM; m++) {
        int row = m0 + ty * TM + m;
        float4 r;
        r.x = acc[m][0] + bv[0];
        r.y = acc[m][1] + bv[1];
        r.z = acc[m][2] + bv[2];
        r.w = acc[m][3] + bv[3];
        *reinterpret_cast<float4*>(&out[(size_t)row * Oz + n0 + tx * TN]) = r;
    }
}

// ---------------------------------------------------------------------------
// Launch: 3 kernels on the same stream (graph-capturable, no syncs/allocs).
// Inputs (metadata order): x (B*I f32), laplacecoeffs (2*O*I*G f32), bias (O f32)
// ---------------------------------------------------------------------------
extern "C" void kernel_launch(void* const* d_in, const int* in_sizes, int n_in,
                              void* d_out, int out_size) {
    const float* x    = (const float*)d_in[0];
    const float* coef = (const float*)d_in[1];
    const float* bias = (const float*)d_in[2];
    float* out = (float*)d_out;

    feat_kernel<<<(Bz * Iz) / 256, 256>>>(x);
    wtrans_kernel<<<Iz * 2, 256>>>(coef);
    dim3 grid(Oz / BN, Bz / BM);   // (4, 32)
    gemm_kernel<<<grid, 256>>>(bias, out);
}

// round 4
// speedup vs baseline: 3.3021x; 3.3021x over previous
#include <cuda_runtime.h>
#include <cuda_bf16.h>
#include <cstdint>

// Problem dims
#define Bz 4096
#define Iz 256
#define Oz 256
#define Kz 8192   // 2 * Iz * 16 ; k = s*4096 + i*16 + g

// Scratch globals (no allocs allowed)
__device__ __nv_bfloat16 g_Ah[(size_t)Bz * Kz];   // feature hi  (64 MB)
__device__ __nv_bfloat16 g_Al[(size_t)Bz * Kz];   // feature lo  (64 MB)
__device__ __nv_bfloat16 g_Wh[(size_t)Oz * Kz];   // weight hi   (4 MB)
__device__ __nv_bfloat16 g_Wl[(size_t)Oz * Kz];   // weight lo   (4 MB)

// ---------------------------------------------------------------- helpers --
__device__ __forceinline__ uint32_t smem_u32(const void* p) {
    uint32_t a;
    asm("{ .reg .u64 t; cvta.to.shared.u64 t, %1; cvt.u32.u64 %0, t; }"
        : "=r"(a) : "l"(p));
    return a;
}
__device__ __forceinline__ void cp16(uint32_t dst, const void* src) {
    asm volatile("cp.async.cg.shared.global [%0], [%1], 16;" :: "r"(dst), "l"(src) : "memory");
}
__device__ __forceinline__ void cp_commit() {
    asm volatile("cp.async.commit_group;" ::: "memory");
}
__device__ __forceinline__ void cp_wait1() {
    asm volatile("cp.async.wait_group 1;" ::: "memory");
}
__device__ __forceinline__ void ldsm4(uint32_t* r, uint32_t a) {
    asm volatile("ldmatrix.sync.aligned.m8n8.x4.shared.b16 {%0,%1,%2,%3}, [%4];"
                 : "=r"(r[0]), "=r"(r[1]), "=r"(r[2]), "=r"(r[3]) : "r"(a));
}
__device__ __forceinline__ void mma16816(float* d, const uint32_t* a, const uint32_t* b) {
    asm volatile(
        "mma.sync.aligned.m16n8k16.row.col.f32.bf16.bf16.f32 "
        "{%0,%1,%2,%3}, {%4,%5,%6,%7}, {%8,%9}, {%0,%1,%2,%3};"
        : "+f"(d[0]), "+f"(d[1]), "+f"(d[2]), "+f"(d[3])
        : "r"(a[0]), "r"(a[1]), "r"(a[2]), "r"(a[3]), "r"(b[0]), "r"(b[1]));
}

// -------------------------------------------------------- feature kernel --
// lambda_g = 0.1 + 0.06 g  =>  geometric recurrence, 4 __expf per (b,i).
// Write bf16 hi/lo features at k = s*4096 + i*16 + g.
__global__ __launch_bounds__(256) void feat_kernel(const float* __restrict__ x) {
    int idx = blockIdx.x * 256 + threadIdx.x;   // b*256 + i
    float xv = x[idx];

    float tn = __expf(-0.06f * xv);
    float tp = __expf( 0.06f * xv);
    float fn = __expf(-0.10f * xv);
    float fp = __expf( 0.10f * xv);

    uint32_t hn[8], ln[8], hp[8], lp[8];
#pragma unroll
    for (int q = 0; q < 8; q++) {
        float f0 = fn; fn *= tn; float f1 = fn; fn *= tn;
        __nv_bfloat16 h0 = __float2bfloat16_rn(f0);
        __nv_bfloat16 h1 = __float2bfloat16_rn(f1);
        __nv_bfloat16 l0 = __float2bfloat16_rn(f0 - __bfloat162float(h0));
        __nv_bfloat16 l1 = __float2bfloat16_rn(f1 - __bfloat162float(h1));
        hn[q] = ((uint32_t)__bfloat16_as_ushort(h1) << 16) | __bfloat16_as_ushort(h0);
        ln[q] = ((uint32_t)__bfloat16_as_ushort(l1) << 16) | __bfloat16_as_ushort(l0);

        float p0 = fp; fp *= tp; float p1 = fp; fp *= tp;
        __nv_bfloat16 H0 = __float2bfloat16_rn(p0);
        __nv_bfloat16 H1 = __float2bfloat16_rn(p1);
        __nv_bfloat16 L0 = __float2bfloat16_rn(p0 - __bfloat162float(H0));
        __nv_bfloat16 L1 = __float2bfloat16_rn(p1 - __bfloat162float(H1));
        hp[q] = ((uint32_t)__bfloat16_as_ushort(H1) << 16) | __bfloat16_as_ushort(H0);
        lp[q] = ((uint32_t)__bfloat16_as_ushort(L1) << 16) | __bfloat16_as_ushort(L0);
    }

    size_t base = ((size_t)(idx >> 8)) * Kz + (size_t)(idx & 255) * 16;
    uint4* dhn = reinterpret_cast<uint4*>(g_Ah + base);
    uint4* dln = reinterpret_cast<uint4*>(g_Al + base);
    uint4* dhp = reinterpret_cast<uint4*>(g_Ah + base + 4096);
    uint4* dlp = reinterpret_cast<uint4*>(g_Al + base + 4096);
    dhn[0] = make_uint4(hn[0], hn[1], hn[2], hn[3]);
    dhn[1] = make_uint4(hn[4], hn[5], hn[6], hn[7]);
    dln[0] = make_uint4(ln[0], ln[1], ln[2], ln[3]);
    dln[1] = make_uint4(ln[4], ln[5], ln[6], ln[7]);
    dhp[0] = make_uint4(hp[0], hp[1], hp[2], hp[3]);
    dhp[1] = make_uint4(hp[4], hp[5], hp[6], hp[7]);
    dlp[0] = make_uint4(lp[0], lp[1], lp[2], lp[3]);
    dlp[1] = make_uint4(lp[4], lp[5], lp[6], lp[7]);
}

// -------------------------------------------------- weight convert kernel --
// C [2][O][I*G] contiguous -> W[o][k], k = s*4096 + (i*16+g). Elementwise.
__global__ __launch_bounds__(256) void wconv_kernel(const float* __restrict__ C) {
    int t = blockIdx.x * 256 + threadIdx.x;
    size_t lin = (size_t)t * 4;
    int s  = (int)(lin >> 20);
    int o  = (int)((lin >> 12) & 255);
    int kp = (int)(lin & 4095);
    float4 v = *reinterpret_cast<const float4*>(C + lin);

    float f[4] = {v.x, v.y, v.z, v.w};
    uint32_t h[2], l[2];
#pragma unroll
    for (int q = 0; q < 2; q++) {
        __nv_bfloat16 h0 = __float2bfloat16_rn(f[q*2+0]);
        __nv_bfloat16 h1 = __float2bfloat16_rn(f[q*2+1]);
        __nv_bfloat16 l0 = __float2bfloat16_rn(f[q*2+0] - __bfloat162float(h0));
        __nv_bfloat16 l1 = __float2bfloat16_rn(f[q*2+1] - __bfloat162float(h1));
        h[q] = ((uint32_t)__bfloat16_as_ushort(h1) << 16) | __bfloat16_as_ushort(h0);
        l[q] = ((uint32_t)__bfloat16_as_ushort(l1) << 16) | __bfloat16_as_ushort(l0);
    }
    size_t op = (size_t)o * Kz + (size_t)s * 4096 + kp;
    *reinterpret_cast<uint2*>(g_Wh + op) = make_uint2(h[0], h[1]);
    *reinterpret_cast<uint2*>(g_Wl + op) = make_uint2(l[0], l[1]);
}

// ------------------------------------------------------- mma.sync GEMM ----
// out[B][O] = Ah*Wh + Ah*Wl + Al*Wh (fp32 accum) + bias
// CTA tile 64x128, K-chunk 64, 3-stage cp.async ring, 8 warps of 32x32.
#define BM 64
#define BN 128
#define NSTG 3
#define STG_BYTES 49152        // Ah 8K | Al 8K | Bh 16K | Bl 16K
#define NCHUNK (Kz / 64)       // 128
#define SMEM_SIZE (NSTG * STG_BYTES + 1024)

// swizzled within-tile byte offset for (row, 16B-chunk ck), 128B rows
#define SWADDR(row, ck) ((uint32_t)((row) * 128 + (((ck) ^ ((row) & 7)) << 4)))

__device__ __forceinline__ void load_stage(uint32_t orig, int s, int c,
                                           int t, int m0, int n0) {
    uint32_t sb = orig + s * STG_BYTES;
    size_t ko = (size_t)c * 64;
#pragma unroll
    for (int j = 0; j < 2; j++) {
        int idx = t + j * 256;
        int row = idx >> 3, ck = idx & 7;
        uint32_t rel = SWADDR(row, ck);
        size_t g = (size_t)(m0 + row) * Kz + ko + ck * 8;
        cp16(sb + rel,        g_Ah + g);
        cp16(sb + 8192 + rel, g_Al + g);
    }
#pragma unroll
    for (int j = 0; j < 4; j++) {
        int idx = t + j * 256;
        int row = idx >> 3, ck = idx & 7;
        uint32_t rel = SWADDR(row, ck);
        size_t g = (size_t)(n0 + row) * Kz + ko + ck * 8;
        cp16(sb + 16384 + rel, g_Wh + g);
        cp16(sb + 32768 + rel, g_Wl + g);
    }
}

__global__ __launch_bounds__(256, 1) void gemm_kernel(const float* __restrict__ bias,
                                                      float* __restrict__ out) {
    extern __shared__ unsigned char smem_raw[];
    uint32_t orig = (smem_u32(smem_raw) + 1023u) & ~1023u;

    int t    = threadIdx.x;
    int lane = t & 31;
    int wid  = t >> 5;
    int wm   = wid & 1;          // 0..1 -> 32-row band
    int wn   = wid >> 1;         // 0..3 -> 32-col band
    int m0   = blockIdx.y * BM;
    int n0   = blockIdx.x * BN;

    float acc[2][4][4];
#pragma unroll
    for (int mt = 0; mt < 2; mt++)
#pragma unroll
        for (int nt = 0; nt < 4; nt++)
#pragma unroll
            for (int r = 0; r < 4; r++) acc[mt][nt][r] = 0.0f;

    // per-lane ldmatrix address components
    int a_row_base = wm * 32 + (lane & 15);   // + mt*16
    int a_ckx      = lane >> 4;               // 0/1: k halves of 16-step
    int b_n_off    = ((lane >> 4) & 1) * 8 + (lane & 7);   // + wn*32 + q*16
    int b_ckx      = (lane >> 3) & 1;

    // prologue
    load_stage(orig, 0, 0, t, m0, n0); cp_commit();
    load_stage(orig, 1, 1, t, m0, n0); cp_commit();

    for (int c = 0; c < NCHUNK; c++) {
        cp_wait1();
        __syncthreads();

        if (c + 2 < NCHUNK) load_stage(orig, (c + 2) % NSTG, c + 2, t, m0, n0);
        cp_commit();

        uint32_t sb = orig + (c % NSTG) * STG_BYTES;
#pragma unroll
        for (int ks = 0; ks < 4; ks++) {
            uint32_t ah[2][4], al[2][4], bh[2][4], bl[2][4];
#pragma unroll
            for (int mt = 0; mt < 2; mt++) {
                int row = a_row_base + mt * 16;
                uint32_t ad = sb + SWADDR(row, ks * 2 + a_ckx);
                ldsm4(ah[mt], ad);
                ldsm4(al[mt], ad + 8192);
            }
#pragma unroll
            for (int q = 0; q < 2; q++) {
                int n = wn * 32 + q * 16 + b_n_off;
                uint32_t bd = sb + 16384 + SWADDR(n, ks * 2 + b_ckx);
                ldsm4(bh[q], bd);          // NON-trans: [o][k] k-contig IS col-major B
                ldsm4(bl[q], bd + 16384);
            }
#pragma unroll
            for (int mt = 0; mt < 2; mt++)
#pragma unroll
                for (int nt = 0; nt < 4; nt++) {
                    int q = nt >> 1, pr = (nt & 1) * 2;
                    mma16816(acc[mt][nt], ah[mt], &bh[q][pr]);
                    mma16816(acc[mt][nt], ah[mt], &bl[q][pr]);
                    mma16816(acc[mt][nt], al[mt], &bh[q][pr]);
                }
        }
        __syncthreads();
    }

    // epilogue: bias + store (fragment layout of m16n8 f32 d-regs)
#pragma unroll
    for (int mt = 0; mt < 2; mt++) {
        int row = m0 + wm * 32 + mt * 16 + (lane >> 2);
#pragma unroll
        for (int nt = 0; nt < 4; nt++) {
            int col = n0 + wn * 32 + nt * 8 + (lane & 3) * 2;
            float2 bv = *reinterpret_cast<const float2*>(bias + col);
            float2 r0, r1;
            r0.x = acc[mt][nt][0] + bv.x;
            r0.y = acc[mt][nt][1] + bv.y;
            r1.x = acc[mt][nt][2] + bv.x;
            r1.y = acc[mt][nt][3] + bv.y;
            *reinterpret_cast<float2*>(out + (size_t)row * Oz + col) = r0;
            *reinterpret_cast<float2*>(out + (size_t)(row + 8) * Oz + col) = r1;
        }
    }
}

// -------------------------------------------------------------- launcher --
extern "C" void kernel_launch(void* const* d_in, const int* in_sizes, int n_in,
                              void* d_out, int out_size) {
    const float* x    = (const float*)d_in[0];
    const float* coef = (const float*)d_in[1];
    const float* bias = (const float*)d_in[2];
    float* out = (float*)d_out;

    static int configured = 0;
    if (!configured) {
        cudaFuncSetAttribute(gemm_kernel,
                             cudaFuncAttributeMaxDynamicSharedMemorySize, SMEM_SIZE);
        configured = 1;
    }

    feat_kernel<<<(Bz * Iz) / 256, 256>>>(x);
    wconv_kernel<<<2048, 256>>>(coef);
    dim3 grid(Oz / BN, Bz / BM);   // (2, 64) = 128 CTAs
    gemm_kernel<<<grid, 256, SMEM_SIZE>>>(bias, out);
}

// round 5
// speedup vs baseline: 5.0455x; 1.5280x over previous
#include <cuda_runtime.h>
#include <cuda_fp16.h>
#include <cstdint>

// Problem dims
#define Bz 4096
#define Iz 256
#define Oz 256
#define Kz 8192   // 2 * Iz * 16 ; k = s*4096 + i*16 + g

// Scratch globals (no allocs allowed)
__device__ __half g_A [(size_t)Bz * Kz];   // features fp16 (64 MB)
__device__ __half g_Wh[(size_t)Oz * Kz];   // weight hi fp16 (4 MB)
__device__ __half g_Wl[(size_t)Oz * Kz];   // weight lo fp16 (4 MB)

// ---------------------------------------------------------------- helpers --
__device__ __forceinline__ uint32_t smem_u32(const void* p) {
    uint32_t a;
    asm("{ .reg .u64 t; cvta.to.shared.u64 t, %1; cvt.u32.u64 %0, t; }"
        : "=r"(a) : "l"(p));
    return a;
}
__device__ __forceinline__ void cp16(uint32_t dst, const void* src) {
    asm volatile("cp.async.cg.shared.global [%0], [%1], 16;" :: "r"(dst), "l"(src) : "memory");
}
__device__ __forceinline__ void cp_commit() {
    asm volatile("cp.async.commit_group;" ::: "memory");
}
__device__ __forceinline__ void cp_wait2() {
    asm volatile("cp.async.wait_group 2;" ::: "memory");
}
__device__ __forceinline__ void ldsm4(uint32_t* r, uint32_t a) {
    asm volatile("ldmatrix.sync.aligned.m8n8.x4.shared.b16 {%0,%1,%2,%3}, [%4];"
                 : "=r"(r[0]), "=r"(r[1]), "=r"(r[2]), "=r"(r[3]) : "r"(a));
}
__device__ __forceinline__ void mma16816(float* d, const uint32_t* a, const uint32_t* b) {
    asm volatile(
        "mma.sync.aligned.m16n8k16.row.col.f32.f16.f16.f32 "
        "{%0,%1,%2,%3}, {%4,%5,%6,%7}, {%8,%9}, {%0,%1,%2,%3};"
        : "+f"(d[0]), "+f"(d[1]), "+f"(d[2]), "+f"(d[3])
        : "r"(a[0]), "r"(a[1]), "r"(a[2]), "r"(a[3]), "r"(b[0]), "r"(b[1]));
}
__device__ __forceinline__ uint32_t packh(__half a, __half b) {
    return ((uint32_t)__half_as_ushort(b) << 16) | __half_as_ushort(a);
}

// -------------------------------------------------------- feature kernel --
// lambda_g = 0.1 + 0.06 g  =>  geometric recurrence, 4 __expf per (b,i).
// Write fp16 features at k = s*4096 + i*16 + g.
__global__ __launch_bounds__(256) void feat_kernel(const float* __restrict__ x) {
    int idx = blockIdx.x * 256 + threadIdx.x;   // b*256 + i
    float xv = x[idx];

    float tn = __expf(-0.06f * xv);
    float tp = __expf( 0.06f * xv);
    float fn = __expf(-0.10f * xv);
    float fp = __expf( 0.10f * xv);

    uint32_t nw[8], pw[8];
#pragma unroll
    for (int q = 0; q < 8; q++) {
        __half n0 = __float2half_rn(fn); fn *= tn;
        __half n1 = __float2half_rn(fn); fn *= tn;
        nw[q] = packh(n0, n1);
        __half p0 = __float2half_rn(fp); fp *= tp;
        __half p1 = __float2half_rn(fp); fp *= tp;
        pw[q] = packh(p0, p1);
    }

    size_t base = ((size_t)(idx >> 8)) * Kz + (size_t)(idx & 255) * 16;
    uint4* dn = reinterpret_cast<uint4*>(g_A + base);          // s=0
    uint4* dp = reinterpret_cast<uint4*>(g_A + base + 4096);   // s=1
    dn[0] = make_uint4(nw[0], nw[1], nw[2], nw[3]);
    dn[1] = make_uint4(nw[4], nw[5], nw[6], nw[7]);
    dp[0] = make_uint4(pw[0], pw[1], pw[2], pw[3]);
    dp[1] = make_uint4(pw[4], pw[5], pw[6], pw[7]);
}

// -------------------------------------------------- weight convert kernel --
// C [2][O][I*G] contiguous -> W[o][k], k = s*4096 + (i*16+g). fp16 hi/lo split.
__global__ __launch_bounds__(256) void wconv_kernel(const float* __restrict__ C) {
    int t = blockIdx.x * 256 + threadIdx.x;
    size_t lin = (size_t)t * 4;
    int s  = (int)(lin >> 20);
    int o  = (int)((lin >> 12) & 255);
    int kp = (int)(lin & 4095);
    float4 v = *reinterpret_cast<const float4*>(C + lin);

    float f[4] = {v.x, v.y, v.z, v.w};
    uint32_t h[2], l[2];
#pragma unroll
    for (int q = 0; q < 2; q++) {
        __half h0 = __float2half_rn(f[q*2+0]);
        __half h1 = __float2half_rn(f[q*2+1]);
        __half l0 = __float2half_rn(f[q*2+0] - __half2float(h0));
        __half l1 = __float2half_rn(f[q*2+1] - __half2float(h1));
        h[q] = packh(h0, h1);
        l[q] = packh(l0, l1);
    }
    size_t op = (size_t)o * Kz + (size_t)s * 4096 + kp;
    *reinterpret_cast<uint2*>(g_Wh + op) = make_uint2(h[0], h[1]);
    *reinterpret_cast<uint2*>(g_Wl + op) = make_uint2(l[0], l[1]);
}

// ------------------------------------------------------- mma.sync GEMM ----
// out[B][O] = A*Wh + A*Wl (fp32 accum) + bias
// CTA tile 64x128, K-chunk 64, 4-stage cp.async ring, 8 warps of 32x32.
#define BM 64
#define BN 128
#define NSTG 4
#define STG_BYTES 40960        // A 8K | Wh 16K | Wl 16K
#define NCHUNK (Kz / 64)       // 128
#define SMEM_SIZE (NSTG * STG_BYTES + 1024)

// swizzled within-tile byte offset for (row, 16B-chunk ck), 128B rows
#define SWADDR(row, ck) ((uint32_t)((row) * 128 + (((ck) ^ ((row) & 7)) << 4)))

__device__ __forceinline__ void load_stage(uint32_t orig, int s, int c,
                                           int t, int m0, int n0) {
    uint32_t sb = orig + s * STG_BYTES;
    size_t ko = (size_t)c * 64;
#pragma unroll
    for (int j = 0; j < 2; j++) {          // A: 64 rows x 8 chunks = 512
        int idx = t + j * 256;
        int row = idx >> 3, ck = idx & 7;
        uint32_t rel = SWADDR(row, ck);
        cp16(sb + rel, g_A + (size_t)(m0 + row) * Kz + ko + ck * 8);
    }
#pragma unroll
    for (int j = 0; j < 4; j++) {          // W: 128 rows x 8 chunks = 1024
        int idx = t + j * 256;
        int row = idx >> 3, ck = idx & 7;
        uint32_t rel = SWADDR(row, ck);
        size_t g = (size_t)(n0 + row) * Kz + ko + ck * 8;
        cp16(sb +  8192 + rel, g_Wh + g);
        cp16(sb + 24576 + rel, g_Wl + g);
    }
}

__global__ __launch_bounds__(256, 1) void gemm_kernel(const float* __restrict__ bias,
                                                      float* __restrict__ out) {
    extern __shared__ unsigned char smem_raw[];
    uint32_t orig = (smem_u32(smem_raw) + 1023u) & ~1023u;

    int t    = threadIdx.x;
    int lane = t & 31;
    int wid  = t >> 5;
    int wm   = wid & 1;          // 0..1 -> 32-row band
    int wn   = wid >> 1;         // 0..3 -> 32-col band
    int m0   = blockIdx.y * BM;
    int n0   = blockIdx.x * BN;

    float acc[2][4][4];
#pragma unroll
    for (int mt = 0; mt < 2; mt++)
#pragma unroll
        for (int nt = 0; nt < 4; nt++)
#pragma unroll
            for (int r = 0; r < 4; r++) acc[mt][nt][r] = 0.0f;

    // per-lane ldmatrix address components
    int a_row_base = wm * 32 + (lane & 15);                 // + mt*16
    int a_ckx      = lane >> 4;                             // k-half select
    int b_n_off    = ((lane >> 4) & 1) * 8 + (lane & 7);    // + wn*32 + q*16
    int b_ckx      = (lane >> 3) & 1;

    // prologue: 3 stages in flight
    load_stage(orig, 0, 0, t, m0, n0); cp_commit();
    load_stage(orig, 1, 1, t, m0, n0); cp_commit();
    load_stage(orig, 2, 2, t, m0, n0); cp_commit();

    for (int c = 0; c < NCHUNK; c++) {
        cp_wait2();
        __syncthreads();

        if (c + 3 < NCHUNK) load_stage(orig, (c + 3) & 3, c + 3, t, m0, n0);
        cp_commit();

        uint32_t sb = orig + (c & 3) * STG_BYTES;
#pragma unroll
        for (int ks = 0; ks < 4; ks++) {
            uint32_t av[2][4], bh[2][4], bl[2][4];
#pragma unroll
            for (int mt = 0; mt < 2; mt++) {
                uint32_t ad = sb + SWADDR(a_row_base + mt * 16, ks * 2 + a_ckx);
                ldsm4(av[mt], ad);
            }
#pragma unroll
            for (int q = 0; q < 2; q++) {
                int n = wn * 32 + q * 16 + b_n_off;
                uint32_t bd = sb + 8192 + SWADDR(n, ks * 2 + b_ckx);
                ldsm4(bh[q], bd);
                ldsm4(bl[q], bd + 16384);
            }
#pragma unroll
            for (int mt = 0; mt < 2; mt++)
#pragma unroll
                for (int nt = 0; nt < 4; nt++) {
                    int q = nt >> 1, pr = (nt & 1) * 2;
                    mma16816(acc[mt][nt], av[mt], &bh[q][pr]);
                    mma16816(acc[mt][nt], av[mt], &bl[q][pr]);
                }
        }
        __syncthreads();
    }

    // epilogue: bias + store (fragment layout of m16n8 f32 d-regs)
#pragma unroll
    for (int mt = 0; mt < 2; mt++) {
        int row = m0 + wm * 32 + mt * 16 + (lane >> 2);
#pragma unroll
        for (int nt = 0; nt < 4; nt++) {
            int col = n0 + wn * 32 + nt * 8 + (lane & 3) * 2;
            float2 bv = *reinterpret_cast<const float2*>(bias + col);
            float2 r0, r1;
            r0.x = acc[mt][nt][0] + bv.x;
            r0.y = acc[mt][nt][1] + bv.y;
            r1.x = acc[mt][nt][2] + bv.x;
            r1.y = acc[mt][nt][3] + bv.y;
            *reinterpret_cast<float2*>(out + (size_t)row * Oz + col) = r0;
            *reinterpret_cast<float2*>(out + (size_t)(row + 8) * Oz + col) = r1;
        }
    }
}

// -------------------------------------------------------------- launcher --
extern "C" void kernel_launch(void* const* d_in, const int* in_sizes, int n_in,
                              void* d_out, int out_size) {
    const float* x    = (const float*)d_in[0];
    const float* coef = (const float*)d_in[1];
    const float* bias = (const float*)d_in[2];
    float* out = (float*)d_out;

    static int configured = 0;
    if (!configured) {
        cudaFuncSetAttribute(gemm_kernel,
                             cudaFuncAttributeMaxDynamicSharedMemorySize, SMEM_SIZE);
        configured = 1;
    }

    feat_kernel<<<(Bz * Iz) / 256, 256>>>(x);
    wconv_kernel<<<2048, 256>>>(coef);
    dim3 grid(Oz / BN, Bz / BM);   // (2, 64) = 128 CTAs
    gemm_kernel<<<grid, 256, SMEM_SIZE>>>(bias, out);
}

// round 6
// speedup vs baseline: 7.3321x; 1.4532x over previous
#include <cuda_runtime.h>
#include <cuda_fp16.h>
#include <cstdint>

// Problem dims
#define Bz 4096
#define Iz 256
#define Oz 256
#define Kz 8192   // 2 * Iz * 16 ; k = s*4096 + i*16 + g

// Scratch globals (no allocs allowed)
__device__ __half g_A[(size_t)Bz * Kz];   // features fp16 (64 MB)
__device__ __half g_W[(size_t)Oz * Kz];   // weights  fp16 (4 MB)

// ---------------------------------------------------------------- helpers --
__device__ __forceinline__ uint32_t smem_u32(const void* p) {
    uint32_t a;
    asm("{ .reg .u64 t; cvta.to.shared.u64 t, %1; cvt.u32.u64 %0, t; }"
        : "=r"(a) : "l"(p));
    return a;
}
__device__ __forceinline__ void cp16(uint32_t dst, const void* src) {
    asm volatile("cp.async.cg.shared.global [%0], [%1], 16;" :: "r"(dst), "l"(src) : "memory");
}
__device__ __forceinline__ void cp_commit() {
    asm volatile("cp.async.commit_group;" ::: "memory");
}
__device__ __forceinline__ void cp_wait2() {
    asm volatile("cp.async.wait_group 2;" ::: "memory");
}
__device__ __forceinline__ void ldsm4(uint32_t* r, uint32_t a) {
    asm volatile("ldmatrix.sync.aligned.m8n8.x4.shared.b16 {%0,%1,%2,%3}, [%4];"
                 : "=r"(r[0]), "=r"(r[1]), "=r"(r[2]), "=r"(r[3]) : "r"(a));
}
__device__ __forceinline__ void mma16816(float* d, const uint32_t* a, const uint32_t* b) {
    asm volatile(
        "mma.sync.aligned.m16n8k16.row.col.f32.f16.f16.f32 "
        "{%0,%1,%2,%3}, {%4,%5,%6,%7}, {%8,%9}, {%0,%1,%2,%3};"
        : "+f"(d[0]), "+f"(d[1]), "+f"(d[2]), "+f"(d[3])
        : "r"(a[0]), "r"(a[1]), "r"(a[2]), "r"(a[3]), "r"(b[0]), "r"(b[1]));
}
__device__ __forceinline__ uint32_t packh(__half a, __half b) {
    return ((uint32_t)__half_as_ushort(b) << 16) | __half_as_ushort(a);
}

// -------------------------------------------------------- feature kernel --
// lambda_g = 0.1 + 0.06 g  =>  geometric recurrence, 4 __expf per (b,i).
// Write fp16 features at k = s*4096 + i*16 + g.
__global__ __launch_bounds__(256) void feat_kernel(const float* __restrict__ x) {
    int idx = blockIdx.x * 256 + threadIdx.x;   // b*256 + i
    float xv = x[idx];

    float tn = __expf(-0.06f * xv);
    float tp = __expf( 0.06f * xv);
    float fn = __expf(-0.10f * xv);
    float fp = __expf( 0.10f * xv);

    uint32_t nw[8], pw[8];
#pragma unroll
    for (int q = 0; q < 8; q++) {
        __half n0 = __float2half_rn(fn); fn *= tn;
        __half n1 = __float2half_rn(fn); fn *= tn;
        nw[q] = packh(n0, n1);
        __half p0 = __float2half_rn(fp); fp *= tp;
        __half p1 = __float2half_rn(fp); fp *= tp;
        pw[q] = packh(p0, p1);
    }

    size_t base = ((size_t)(idx >> 8)) * Kz + (size_t)(idx & 255) * 16;
    uint4* dn = reinterpret_cast<uint4*>(g_A + base);          // s=0
    uint4* dp = reinterpret_cast<uint4*>(g_A + base + 4096);   // s=1
    dn[0] = make_uint4(nw[0], nw[1], nw[2], nw[3]);
    dn[1] = make_uint4(nw[4], nw[5], nw[6], nw[7]);
    dp[0] = make_uint4(pw[0], pw[1], pw[2], pw[3]);
    dp[1] = make_uint4(pw[4], pw[5], pw[6], pw[7]);
}

// -------------------------------------------------- weight convert kernel --
// C [2][O][I*G] contiguous -> W[o][k], k = s*4096 + (i*16+g). fp16.
__global__ __launch_bounds__(256) void wconv_kernel(const float* __restrict__ C) {
    int t = blockIdx.x * 256 + threadIdx.x;
    size_t lin = (size_t)t * 4;
    int s  = (int)(lin >> 20);
    int o  = (int)((lin >> 12) & 255);
    int kp = (int)(lin & 4095);
    float4 v = *reinterpret_cast<const float4*>(C + lin);

    uint32_t h0 = packh(__float2half_rn(v.x), __float2half_rn(v.y));
    uint32_t h1 = packh(__float2half_rn(v.z), __float2half_rn(v.w));
    size_t op = (size_t)o * Kz + (size_t)s * 4096 + kp;
    *reinterpret_cast<uint2*>(g_W + op) = make_uint2(h0, h1);
}

// ------------------------------------------------------- mma.sync GEMM ----
// out[B][O] = A*W (fp32 accum) + bias
// CTA tile 64x128, K-chunk 64, 4-stage cp.async ring, 8 warps of 32x32.
#define BM 64
#define BN 128
#define NSTG 4
#define STG_BYTES 24576        // A 8K | W 16K
#define NCHUNK (Kz / 64)       // 128
#define SMEM_SIZE (NSTG * STG_BYTES + 1024)

// swizzled within-tile byte offset for (row, 16B-chunk ck), 128B rows
#define SWADDR(row, ck) ((uint32_t)((row) * 128 + (((ck) ^ ((row) & 7)) << 4)))

__device__ __forceinline__ void load_stage(uint32_t orig, int s, int c,
                                           int t, int m0, int n0) {
    uint32_t sb = orig + s * STG_BYTES;
    size_t ko = (size_t)c * 64;
#pragma unroll
    for (int j = 0; j < 2; j++) {          // A: 64 rows x 8 chunks = 512
        int idx = t + j * 256;
        int row = idx >> 3, ck = idx & 7;
        cp16(sb + SWADDR(row, ck), g_A + (size_t)(m0 + row) * Kz + ko + ck * 8);
    }
#pragma unroll
    for (int j = 0; j < 4; j++) {          // W: 128 rows x 8 chunks = 1024
        int idx = t + j * 256;
        int row = idx >> 3, ck = idx & 7;
        cp16(sb + 8192 + SWADDR(row, ck), g_W + (size_t)(n0 + row) * Kz + ko + ck * 8);
    }
}

__global__ __launch_bounds__(256, 1) void gemm_kernel(const float* __restrict__ bias,
                                                      float* __restrict__ out) {
    extern __shared__ unsigned char smem_raw[];
    uint32_t orig = (smem_u32(smem_raw) + 1023u) & ~1023u;

    int t    = threadIdx.x;
    int lane = t & 31;
    int wid  = t >> 5;
    int wm   = wid & 1;          // 0..1 -> 32-row band
    int wn   = wid >> 1;         // 0..3 -> 32-col band
    int m0   = blockIdx.y * BM;
    int n0   = blockIdx.x * BN;

    float acc[2][4][4];
#pragma unroll
    for (int mt = 0; mt < 2; mt++)
#pragma unroll
        for (int nt = 0; nt < 4; nt++)
#pragma unroll
            for (int r = 0; r < 4; r++) acc[mt][nt][r] = 0.0f;

    // per-lane ldmatrix address components
    int a_row_base = wm * 32 + (lane & 15);                 // + mt*16
    int a_ckx      = lane >> 4;                             // k-half select
    int b_n_off    = ((lane >> 4) & 1) * 8 + (lane & 7);    // + wn*32 + q*16
    int b_ckx      = (lane >> 3) & 1;

    // prologue: 3 stages in flight
    load_stage(orig, 0, 0, t, m0, n0); cp_commit();
    load_stage(orig, 1, 1, t, m0, n0); cp_commit();
    load_stage(orig, 2, 2, t, m0, n0); cp_commit();

    for (int c = 0; c < NCHUNK; c++) {
        cp_wait2();
        __syncthreads();

        if (c + 3 < NCHUNK) load_stage(orig, (c + 3) & 3, c + 3, t, m0, n0);
        cp_commit();

        uint32_t sb = orig + (c & 3) * STG_BYTES;
#pragma unroll
        for (int ks = 0; ks < 4; ks++) {
            uint32_t av[2][4], bv[2][4];
#pragma unroll
            for (int mt = 0; mt < 2; mt++)
                ldsm4(av[mt], sb + SWADDR(a_row_base + mt * 16, ks * 2 + a_ckx));
#pragma unroll
            for (int q = 0; q < 2; q++) {
                int n = wn * 32 + q * 16 + b_n_off;
                ldsm4(bv[q], sb + 8192 + SWADDR(n, ks * 2 + b_ckx));
            }
#pragma unroll
            for (int mt = 0; mt < 2; mt++)
#pragma unroll
                for (int nt = 0; nt < 4; nt++) {
                    int q = nt >> 1, pr = (nt & 1) * 2;
                    mma16816(acc[mt][nt], av[mt], &bv[q][pr]);
                }
        }
        __syncthreads();
    }

    // epilogue: bias + store (fragment layout of m16n8 f32 d-regs)
#pragma unroll
    for (int mt = 0; mt < 2; mt++) {
        int row = m0 + wm * 32 + mt * 16 + (lane >> 2);
#pragma unroll
        for (int nt = 0; nt < 4; nt++) {
            int col = n0 + wn * 32 + nt * 8 + (lane & 3) * 2;
            float2 bv = *reinterpret_cast<const float2*>(bias + col);
            float2 r0, r1;
            r0.x = acc[mt][nt][0] + bv.x;
            r0.y = acc[mt][nt][1] + bv.y;
            r1.x = acc[mt][nt][2] + bv.x;
            r1.y = acc[mt][nt][3] + bv.y;
            *reinterpret_cast<float2*>(out + (size_t)row * Oz + col) = r0;
            *reinterpret_cast<float2*>(out + (size_t)(row + 8) * Oz + col) = r1;
        }
    }
}

// -------------------------------------------------------------- launcher --
extern "C" void kernel_launch(void* const* d_in, const int* in_sizes, int n_in,
                              void* d_out, int out_size) {
    const float* x    = (const float*)d_in[0];
    const float* coef = (const float*)d_in[1];
    const float* bias = (const float*)d_in[2];
    float* out = (float*)d_out;

    static int configured = 0;
    if (!configured) {
        cudaFuncSetAttribute(gemm_kernel,
                             cudaFuncAttributeMaxDynamicSharedMemorySize, SMEM_SIZE);
        configured = 1;
    }

    feat_kernel<<<(Bz * Iz) / 256, 256>>>(x);
    wconv_kernel<<<2048, 256>>>(coef);
    dim3 grid(Oz / BN, Bz / BM);   // (2, 64) = 128 CTAs
    gemm_kernel<<<grid, 256, SMEM_SIZE>>>(bias, out);
}